// round 14
// baseline (speedup 1.0000x reference)
#include <cuda_runtime.h>

#define XSIZE 256

#define SINCOSV(P, S, C)                                              \
    asm volatile("sin.approx.f32 %0, %2;\n\t"                         \
                 "cos.approx.f32 %1, %2;"                             \
                 : "=f"(S), "=f"(C) : "f"(P));

#define PREP(H, Y0, Y1, Y2, Y3)                                       \
    {                                                                 \
        const float ap = (Y3) + (Y2), am = (Y3) - (Y2);               \
        const float bp = (Y1) + (Y0), bm = (Y1) - (Y0);               \
        H[0] = am - bp; H[1] = am - bm; H[2] = am + bm; H[3] = am + bp; \
        H[4] = ap - bp; H[5] = ap - bm; H[6] = ap + bm; H[7] = ap + bp; \
    }

#define EMIT(VR, VI, H, E)                                            \
    {                                                                 \
        const float he = H[E];                                        \
        const float p1 = __fmaf_rn(he, -he, -he);                     \
        const float p0 = __fmaf_rn(he, -he,  he);                     \
        SINCOSV(p1, VI[8 | (E)], VR[8 | (E)])                         \
        SINCOSV(p0, VI[(E) ^ 7], VR[(E) ^ 7])                         \
    }

#define BF(VR, VI, Q, M, TQ)                                          \
    {                                                                 \
        const int j0 = (((M) >> (Q)) << ((Q) + 1)) | ((M) & ((1 << (Q)) - 1)); \
        const int j1 = j0 | (1 << (Q));                               \
        const float ar = VR[j0], ai = VI[j0];                         \
        const float br = VR[j1], bim = VI[j1];                        \
        VR[j0] = __fmaf_rn( (TQ), bim, ar);                           \
        VI[j0] = __fmaf_rn(-(TQ), br,  ai);                           \
        VR[j1] = __fmaf_rn( (TQ), ai,  br);                           \
        VI[j1] = __fmaf_rn(-(TQ), ar,  bim);                          \
    }

#define LH(VR, VI, Q, MB, TQ)                                         \
    BF(VR, VI, Q, (MB) + 0, TQ) BF(VR, VI, Q, (MB) + 1, TQ)           \
    BF(VR, VI, Q, (MB) + 2, TQ) BF(VR, VI, Q, (MB) + 3, TQ)

#define READOUT(VR, VI, O, SC)                                        \
    {                                                                 \
        float o0 = 0.f, o1 = 0.f, o2 = 0.f, o3 = 0.f;                 \
        _Pragma("unroll")                                             \
        for (int k = 0; k < 16; k++) {                                \
            const float p = __fmaf_rn(VR[k], VR[k], VI[k] * VI[k]);   \
            if (__popc(k & 0xF) & 1) o0 += p;                         \
            if (__popc(k & 0x7) & 1) o1 += p;                         \
            if (__popc(k & 0x3) & 1) o2 += p;                         \
            if (__popc(k & 0xE) & 1) o3 += p;                         \
        }                                                             \
        O.x = (SC) * o0; O.y = (SC) * o1;                             \
        O.z = (SC) * o2; O.w = (SC) * o3;                             \
    }

// R13 pipeline + randomized warp start-skew to break SMSP-wide phase locking
// between the MUFU (sincos) and FMA (butterfly) program phases.
__global__ __launch_bounds__(64) void qconv_kernel11(const float* __restrict__ x,
                                                     const float* __restrict__ w,
                                                     float* __restrict__ out)
{
    __shared__ float sh[5];
    if (threadIdx.x == 0) {
        float C = 1.0f;
#pragma unroll
        for (int q = 0; q < 4; q++) {
            float cq, sq;
            __sincosf(0.5f * __ldg(w + q), &sq, &cq);
            sh[q] = __fdividef(sq, cq);     // tan(w_q/2)
            C *= cq;
        }
        sh[4] = 0.0625f * C * C;
    }
    __syncthreads();
    const float u0 = sh[0], u1 = sh[1], u2 = sh[2], u3 = sh[3];
    float scale = sh[4];

    const int t  = threadIdx.x;
    const int bi = blockIdx.x;              // b*128 + i
    const int i  = bi & 127;
    const size_t base = ((size_t)(bi >> 7) * XSIZE + 2 * i) * XSIZE + 4 * t;
    const float4 r0 = *reinterpret_cast<const float4*>(x + base);
    const float4 r1 = *reinterpret_cast<const float4*>(x + base + XSIZE);

    // ── phase-randomizing start skew: hash(block, warp) -> 0..150 dependent
    // FADDs (~0..600 cyc). Decorrelates program phase across warps AND waves.
    {
        const int wid = t >> 5;
        const int iters = (((bi * 5 + wid) & 15)) * 10;   // 0..150
        float dly = r0.x;
        for (int d = 0; d < iters; d++)
            asm volatile("add.f32 %0, %0, 0F00000000;" : "+f"(dly));
        // consume dly (×0) so the chain cannot be eliminated
        asm("fma.rn.f32 %0, %1, 0F00000000, %0;" : "+f"(scale) : "f"(dly));
    }

    float hA[8], hB[8];
    PREP(hA, 0.5f * r0.x, 0.5f * r0.y, 0.5f * r1.x, 0.5f * r1.y);
    PREP(hB, 0.5f * r0.z, 0.5f * r0.w, 0.5f * r1.z, 0.5f * r1.w);

    float vrA[16], viA[16], vrB[16], viB[16];

    // window 1: A phases (MUFU)
    EMIT(vrA, viA, hA, 0) EMIT(vrA, viA, hA, 1)
    EMIT(vrA, viA, hA, 2) EMIT(vrA, viA, hA, 3)
    EMIT(vrA, viA, hA, 4) EMIT(vrA, viA, hA, 5)
    EMIT(vrA, viA, hA, 6) EMIT(vrA, viA, hA, 7)

    // window 2: B phases (MUFU, pinned) interleaved with A butterflies (FMA)
    EMIT(vrB, viB, hB, 0) LH(vrA, viA, 0, 0, u0)
    EMIT(vrB, viB, hB, 1) LH(vrA, viA, 0, 4, u0)
    EMIT(vrB, viB, hB, 2) LH(vrA, viA, 1, 0, u1)
    EMIT(vrB, viB, hB, 3) LH(vrA, viA, 1, 4, u1)
    EMIT(vrB, viB, hB, 4) LH(vrA, viA, 2, 0, u2)
    EMIT(vrB, viB, hB, 5) LH(vrA, viA, 2, 4, u2)
    EMIT(vrB, viB, hB, 6) LH(vrA, viA, 3, 0, u3)
    EMIT(vrB, viB, hB, 7) LH(vrA, viA, 3, 4, u3)

    // window 3: A readout + all of B's FMA work
    float4 oa, ob;
    READOUT(vrA, viA, oa, scale)

    LH(vrB, viB, 0, 0, u0) LH(vrB, viB, 0, 4, u0)
    LH(vrB, viB, 1, 0, u1) LH(vrB, viB, 1, 4, u1)
    LH(vrB, viB, 2, 0, u2) LH(vrB, viB, 2, 4, u2)
    LH(vrB, viB, 3, 0, u3) LH(vrB, viB, 3, 4, u3)
    READOUT(vrB, viB, ob, scale)

    float* dst = out + (size_t)bi * 512 + 8 * t;
    reinterpret_cast<float4*>(dst)[0] = oa;
    reinterpret_cast<float4*>(dst)[1] = ob;
}

extern "C" void kernel_launch(void* const* d_in, const int* in_sizes, int n_in,
                              void* d_out, int out_size)
{
    const float* x = (const float*)d_in[0];
    const float* w = (const float*)d_in[1];
    float* out = (float*)d_out;
    const int batch = in_sizes[0] / (XSIZE * XSIZE);
    qconv_kernel11<<<batch * 128, 64>>>(x, w, out);
}

// round 15
// speedup vs baseline: 1.1212x; 1.1212x over previous
#include <cuda_runtime.h>

typedef unsigned long long u64;
#define XSIZE 256

__device__ __forceinline__ u64 pk(float lo, float hi) {
    u64 r; asm("mov.b64 %0,{%1,%2};" : "=l"(r) : "f"(lo), "f"(hi)); return r;
}
__device__ __forceinline__ void upk(float& lo, float& hi, u64 v) {
    asm("mov.b64 {%0,%1},%2;" : "=f"(lo), "=f"(hi) : "l"(v));
}
__device__ __forceinline__ u64 fma2(u64 a, u64 b, u64 c) {
    u64 d; asm("fma.rn.f32x2 %0,%1,%2,%3;" : "=l"(d) : "l"(a), "l"(b), "l"(c)); return d;
}
__device__ __forceinline__ u64 mul2(u64 a, u64 b) {
    u64 d; asm("mul.rn.f32x2 %0,%1,%2;" : "=l"(d) : "l"(a), "l"(b)); return d;
}
__device__ __forceinline__ u64 add2(u64 a, u64 b) {
    u64 d; asm("add.rn.f32x2 %0,%1,%2;" : "=l"(d) : "l"(a), "l"(b)); return d;
}

#define SINCOSV(P, S, C)                                              \
    asm volatile("sin.approx.f32 %0, %2;\n\t"                         \
                 "cos.approx.f32 %1, %2;"                             \
                 : "=f"(S), "=f"(C) : "f"(P));

// h_e = y3 ± y2 ± y1 ± y0 on halved inputs (h = t/2)
#define PREP(H, Y0, Y1, Y2, Y3)                                       \
    {                                                                 \
        const float ap = (Y3) + (Y2), am = (Y3) - (Y2);               \
        const float bp = (Y1) + (Y0), bm = (Y1) - (Y0);               \
        H[0] = am - bp; H[1] = am - bm; H[2] = am + bm; H[3] = am + bp; \
        H[4] = ap - bp; H[5] = ap - bm; H[6] = ap + bm; H[7] = ap + bp; \
    }

// 64 threads/block; each thread carries TWO patches packed into f32x2 lanes.
// Phases (MUFU) are scalar per lane; ALL other math is packed FFMA2/FADD2,
// halving the non-MUFU issue count per patch.
__global__ __launch_bounds__(64) void qconv_kernel12(const float* __restrict__ x,
                                                     const float* __restrict__ w,
                                                     float* __restrict__ out)
{
    __shared__ float sh[5];
    if (threadIdx.x == 0) {
        float C = 1.0f;
#pragma unroll
        for (int q = 0; q < 4; q++) {
            float cq, sq;
            __sincosf(0.5f * __ldg(w + q), &sq, &cq);
            sh[q] = __fdividef(sq, cq);     // tan(w_q/2)
            C *= cq;
        }
        sh[4] = 0.0625f * C * C;            // prod cos^2 folded into prob scale
    }
    __syncthreads();

    const int t  = threadIdx.x;
    const int bi = blockIdx.x;              // b*128 + i
    const int i  = bi & 127;
    const size_t base = ((size_t)(bi >> 7) * XSIZE + 2 * i) * XSIZE + 4 * t;
    const float4 r0 = *reinterpret_cast<const float4*>(x + base);
    const float4 r1 = *reinterpret_cast<const float4*>(x + base + XSIZE);

    float hA[8], hB[8];
    PREP(hA, 0.5f * r0.x, 0.5f * r0.y, 0.5f * r1.x, 0.5f * r1.y);
    PREP(hB, 0.5f * r0.z, 0.5f * r0.w, 0.5f * r1.z, 0.5f * r1.w);

    // diag pair (8|e, e^7): phi = -h^2 ∓ h (global phase dropped).
    // Scalar sincos per lane, results packed into the f32x2 state.
    u64 vr[16], vi[16];
#pragma unroll
    for (int e = 0; e < 8; e++) {
        const float ha = hA[e], hb = hB[e];
        const float p1a = __fmaf_rn(ha, -ha, -ha);
        const float p0a = __fmaf_rn(ha, -ha,  ha);
        const float p1b = __fmaf_rn(hb, -hb, -hb);
        const float p0b = __fmaf_rn(hb, -hb,  hb);
        float sa, ca, sb, cb;
        SINCOSV(p1a, sa, ca)
        SINCOSV(p1b, sb, cb)
        vi[8 | e] = pk(sa, sb);
        vr[8 | e] = pk(ca, cb);
        SINCOSV(p0a, sa, ca)
        SINCOSV(p0b, sb, cb)
        vi[e ^ 7] = pk(sa, sb);
        vr[e ^ 7] = pk(ca, cb);
    }

    // packed RX butterflies, tangent form (4 FFMA2 each)
    u64 TQ[4], NQ[4];
#pragma unroll
    for (int q = 0; q < 4; q++) {
        const float uq = sh[q];
        TQ[q] = pk(uq, uq);
        NQ[q] = TQ[q] ^ 0x8000000080000000ULL;
    }
#pragma unroll
    for (int q = 0; q < 4; q++) {
        const u64 tq = TQ[q], nq = NQ[q];
#pragma unroll
        for (int m = 0; m < 8; m++) {
            const int j0 = ((m >> q) << (q + 1)) | (m & ((1 << q) - 1));
            const int j1 = j0 | (1 << q);
            const u64 ar = vr[j0], ai = vi[j0];
            const u64 br = vr[j1], bim = vi[j1];
            vr[j0] = fma2(tq, bim, ar);
            vi[j0] = fma2(nq, br,  ai);
            vr[j1] = fma2(tq, ai,  br);
            vi[j1] = fma2(nq, ar,  bim);
        }
    }

    // CNOT ring + per-qubit Z readout = parity-masked probability sums (packed)
    u64 o0 = 0ULL, o1 = 0ULL, o2 = 0ULL, o3 = 0ULL;
#pragma unroll
    for (int k = 0; k < 16; k++) {
        const u64 p = fma2(vr[k], vr[k], mul2(vi[k], vi[k]));
        if (__popc(k & 0xF) & 1) o0 = add2(o0, p);
        if (__popc(k & 0x7) & 1) o1 = add2(o1, p);
        if (__popc(k & 0x3) & 1) o2 = add2(o2, p);
        if (__popc(k & 0xE) & 1) o3 = add2(o3, p);
    }

    const float sc = sh[4];
    const u64 SC = pk(sc, sc);
    float4 oa, ob;
    upk(oa.x, ob.x, mul2(o0, SC));
    upk(oa.y, ob.y, mul2(o1, SC));
    upk(oa.z, ob.z, mul2(o2, SC));
    upk(oa.w, ob.w, mul2(o3, SC));

    float* dst = out + (size_t)bi * 512 + 8 * t;
    reinterpret_cast<float4*>(dst)[0] = oa;
    reinterpret_cast<float4*>(dst)[1] = ob;
}

extern "C" void kernel_launch(void* const* d_in, const int* in_sizes, int n_in,
                              void* d_out, int out_size)
{
    const float* x = (const float*)d_in[0];
    const float* w = (const float*)d_in[1];
    float* out = (float*)d_out;
    const int batch = in_sizes[0] / (XSIZE * XSIZE);
    qconv_kernel12<<<batch * 128, 64>>>(x, w, out);
}

// round 16
// speedup vs baseline: 1.1255x; 1.0038x over previous
#include <cuda_runtime.h>

#define XSIZE 256

#define SINCOSV(P, S, C)                                              \
    asm volatile("sin.approx.f32 %0, %2;\n\t"                         \
                 "cos.approx.f32 %1, %2;"                             \
                 : "=f"(S), "=f"(C) : "f"(P));

// diag pair (8|e, e^7): h from bases, phi = -h^2 ∓ h (global phase dropped)
#define EMIT1(VR, VI, AP, AM, BP, BM, E) {                            \
    const float he_ = ((E) & 4 ? (AP) : (AM)) +                       \
        (((E) & 3) == 0 ? -(BP) : ((E) & 3) == 1 ? -(BM)              \
         : ((E) & 3) == 2 ? (BM) : (BP));                             \
    const float p1_ = __fmaf_rn(he_, -he_, -he_);                     \
    const float p0_ = __fmaf_rn(he_, -he_,  he_);                     \
    SINCOSV(p1_, VI[8 | (E)], VR[8 | (E)])                            \
    SINCOSV(p0_, VI[(E) ^ 7], VR[(E) ^ 7]) }

// tangent-form RX butterfly (4 FFMA)
#define BF(VR, VI, Q, M, TQ) {                                        \
    const int j0_ = (((M) >> (Q)) << ((Q) + 1)) | ((M) & ((1 << (Q)) - 1)); \
    const int j1_ = j0_ | (1 << (Q));                                 \
    const float ar_ = VR[j0_], ai_ = VI[j0_];                         \
    const float br_ = VR[j1_], bi_ = VI[j1_];                         \
    VR[j0_] = __fmaf_rn( (TQ), bi_, ar_);                             \
    VI[j0_] = __fmaf_rn(-(TQ), br_, ai_);                             \
    VR[j1_] = __fmaf_rn( (TQ), ai_, br_);                             \
    VI[j1_] = __fmaf_rn(-(TQ), ar_, bi_); }

#define LH(VR, VI, Q, MB, TQ)                                         \
    BF(VR, VI, Q, (MB) + 0, TQ) BF(VR, VI, Q, (MB) + 1, TQ)           \
    BF(VR, VI, Q, (MB) + 2, TQ) BF(VR, VI, Q, (MB) + 3, TQ)

// readout quarter: parity-masked probability accumulation for k=K0..K0+3
#define ROQ(VR, VI, K0) { _Pragma("unroll")                           \
    for (int k = (K0); k < (K0) + 4; k++) {                           \
        const float p_ = __fmaf_rn(VR[k], VR[k], VI[k] * VI[k]);      \
        if (__popc(k & 0xF) & 1) o0 += p_;                            \
        if (__popc(k & 0x7) & 1) o1 += p_;                            \
        if (__popc(k & 0x3) & 1) o2 += p_;                            \
        if (__popc(k & 0xE) & 1) o3 += p_; } }

#define LOADX(R, RA, RB) {                                            \
    const size_t base_ = ((size_t)b * XSIZE + 2 * (size_t)(i0 + (R))) * XSIZE + 2 * col; \
    RA = *reinterpret_cast<const float2*>(x + base_);                 \
    RB = *reinterpret_cast<const float2*>(x + base_ + XSIZE); }

#define PREPX(RA, RB, AP, AM, BP, BM) {                               \
    const float y0_ = 0.5f * RA.x, y1_ = 0.5f * RA.y;                 \
    const float y2_ = 0.5f * RB.x, y3_ = 0.5f * RB.y;                 \
    AP = y3_ + y2_; AM = y3_ - y2_; BP = y1_ + y0_; BM = y1_ - y0_; }

#define STOREX(R) { float4 o_;                                        \
    o_.x = scale * o0; o_.y = scale * o1;                             \
    o_.z = scale * o2; o_.w = scale * o3;                             \
    reinterpret_cast<float4*>(out)[((size_t)b * 128 + (i0 + (R))) * 128 + col] = o_; }

// pipeline body: EMIT next patch (MUFU, pinned) interleaved with all FMA work
// (butterflies + readout) of the current patch.
#define BODY(VRN, VIN, AP, AM, BP, BM, VRC, VIC, RC) {                \
    float o0 = 0.f, o1 = 0.f, o2 = 0.f, o3 = 0.f;                     \
    EMIT1(VRN, VIN, AP, AM, BP, BM, 0) LH(VRC, VIC, 0, 0, u0) LH(VRC, VIC, 0, 4, u0) \
    EMIT1(VRN, VIN, AP, AM, BP, BM, 1) LH(VRC, VIC, 1, 0, u1) LH(VRC, VIC, 1, 4, u1) \
    EMIT1(VRN, VIN, AP, AM, BP, BM, 2) LH(VRC, VIC, 2, 0, u2) LH(VRC, VIC, 2, 4, u2) \
    EMIT1(VRN, VIN, AP, AM, BP, BM, 3) LH(VRC, VIC, 3, 0, u3) LH(VRC, VIC, 3, 4, u3) \
    EMIT1(VRN, VIN, AP, AM, BP, BM, 4) ROQ(VRC, VIC, 0)               \
    EMIT1(VRN, VIN, AP, AM, BP, BM, 5) ROQ(VRC, VIC, 4)               \
    EMIT1(VRN, VIN, AP, AM, BP, BM, 6) ROQ(VRC, VIC, 8)               \
    EMIT1(VRN, VIN, AP, AM, BP, BM, 7) ROQ(VRC, VIC, 12)              \
    STOREX(RC) }

#define TAILWORK(VRC, VIC, RC) {                                      \
    float o0 = 0.f, o1 = 0.f, o2 = 0.f, o3 = 0.f;                     \
    LH(VRC, VIC, 0, 0, u0) LH(VRC, VIC, 0, 4, u0)                     \
    LH(VRC, VIC, 1, 0, u1) LH(VRC, VIC, 1, 4, u1)                     \
    LH(VRC, VIC, 2, 0, u2) LH(VRC, VIC, 2, 4, u2)                     \
    LH(VRC, VIC, 3, 0, u3) LH(VRC, VIC, 3, 4, u3)                     \
    ROQ(VRC, VIC, 0) ROQ(VRC, VIC, 4) ROQ(VRC, VIC, 8) ROQ(VRC, VIC, 12) \
    STOREX(RC) }

// 128 threads/block (thread = patch column); block covers 4 patch rows via a
// fully unrolled 4-deep software pipeline: steady state issues the next
// patch's sincos (MUFU) against the current patch's FMA work.
__global__ __launch_bounds__(128) void qconv_kernel13(const float* __restrict__ x,
                                                      const float* __restrict__ w,
                                                      float* __restrict__ out)
{
    __shared__ float sh[5];
    if (threadIdx.x == 0) {
        float C = 1.0f;
#pragma unroll
        for (int q = 0; q < 4; q++) {
            float cq, sq;
            __sincosf(0.5f * __ldg(w + q), &sq, &cq);
            sh[q] = __fdividef(sq, cq);     // tan(w_q/2)
            C *= cq;
        }
        sh[4] = 0.0625f * C * C;            // prod cos^2 folded into prob scale
    }
    __syncthreads();
    const float u0 = sh[0], u1 = sh[1], u2 = sh[2], u3 = sh[3];
    const float scale = sh[4];

    const int col = threadIdx.x;
    const int b   = blockIdx.x >> 5;
    const int i0  = (blockIdx.x & 31) * 4;   // rows i0..i0+3

    float2 La, Lb, Na, Nb;
    float vr0[16], vi0[16], vr1[16], vi1[16];
    float ap0, am0, bp0, bm0, ap1, am1, bp1, bm1;

    // prolog: row0 phases (head MUFU), prefetch rows 1 and 2 under it
    LOADX(0, La, Lb)
    PREPX(La, Lb, ap0, am0, bp0, bm0)
    LOADX(1, Na, Nb)
    EMIT1(vr0, vi0, ap0, am0, bp0, bm0, 0)
    EMIT1(vr0, vi0, ap0, am0, bp0, bm0, 1)
    EMIT1(vr0, vi0, ap0, am0, bp0, bm0, 2)
    EMIT1(vr0, vi0, ap0, am0, bp0, bm0, 3)
    EMIT1(vr0, vi0, ap0, am0, bp0, bm0, 4)
    EMIT1(vr0, vi0, ap0, am0, bp0, bm0, 5)
    EMIT1(vr0, vi0, ap0, am0, bp0, bm0, 6)
    EMIT1(vr0, vi0, ap0, am0, bp0, bm0, 7)
    PREPX(Na, Nb, ap1, am1, bp1, bm1)
    LOADX(2, La, Lb)

    // body 0: emit row1 -> S1, work row0 (S0), store row0
    BODY(vr1, vi1, ap1, am1, bp1, bm1, vr0, vi0, 0)
    PREPX(La, Lb, ap0, am0, bp0, bm0)
    LOADX(3, Na, Nb)

    // body 1: emit row2 -> S0, work row1 (S1), store row1
    BODY(vr0, vi0, ap0, am0, bp0, bm0, vr1, vi1, 1)
    PREPX(Na, Nb, ap1, am1, bp1, bm1)

    // body 2: emit row3 -> S1, work row2 (S0), store row2
    BODY(vr1, vi1, ap1, am1, bp1, bm1, vr0, vi0, 2)

    // tail: work row3 (S1), store row3
    TAILWORK(vr1, vi1, 3)
}

extern "C" void kernel_launch(void* const* d_in, const int* in_sizes, int n_in,
                              void* d_out, int out_size)
{
    const float* x = (const float*)d_in[0];
    const float* w = (const float*)d_in[1];
    float* out = (float*)d_out;
    const int batch = in_sizes[0] / (XSIZE * XSIZE);
    qconv_kernel13<<<batch * 32, 128>>>(x, w, out);
}